// round 3
// baseline (speedup 1.0000x reference)
#include <cuda_runtime.h>
#include <cstdint>

#define EMBED     1024
#define STEPS     8
#define NF        16     // 2*STEPS features
#define NFP       8      // f32x2 feature pairs
#define TOK_TILE  64     // tokens per CTA
#define NTHREADS  512    // 512 threads * 2 dims = 1024 embed dims
#define DPT       2      // embed dims per thread

__device__ __forceinline__ unsigned long long pack2(float a, float b) {
    unsigned long long r;
    asm("mov.b64 %0, {%1, %2};" : "=l"(r) : "f"(a), "f"(b));
    return r;
}

__global__ void __launch_bounds__(NTHREADS, 2)
fractal_embed_kernel(const int*   __restrict__ token_ids,
                     const float* __restrict__ c_table,
                     const float* __restrict__ W,
                     const float* __restrict__ scale_p,
                     float*       __restrict__ out,
                     int n_tokens)
{
    __shared__ __align__(16) float feats_s[TOK_TILE][NF];

    const int tid      = threadIdx.x;
    const int tok_base = blockIdx.x * TOK_TILE;
    if (tok_base >= n_tokens) return;
    const float scale  = *scale_p;

    // ---- Phase A: Julia features for this CTA's token tile (64 threads) ----
    if (tid < TOK_TILE && tok_base + tid < n_tokens) {
        const int   tok = token_ids[tok_base + tid];
        const float cr  = c_table[2 * tok];
        const float ci  = c_table[2 * tok + 1];
        float zr = 0.f, zi = 0.f;
        #pragma unroll
        for (int s = 0; s < STEPS; ++s) {
            const float nzr = zr * zr - zi * zi + cr;
            const float nzi = 2.f * zr * zi + ci;
            zr = nzr; zi = nzi;
            feats_s[tid][2 * s]     = zr;
            feats_s[tid][2 * s + 1] = zi;
        }
    }

    // ---- Per-thread W slice (2 rows x 16 feats), scale folded, f32x2-packed ----
    const int d0 = tid * DPT;
    unsigned long long wreg[DPT][NFP];   // 16 x u64 = 32 registers
    {
        const float2* wp = reinterpret_cast<const float2*>(W + (size_t)d0 * NF);
        #pragma unroll
        for (int j = 0; j < DPT; ++j) {
            #pragma unroll
            for (int p = 0; p < NFP; ++p) {
                float2 w = wp[j * NFP + p];
                wreg[j][p] = pack2(w.x * scale, w.y * scale);
            }
        }
    }
    __syncthreads();

    // ---- Phase B: sweep tokens; running output pointer (stride 4KB) ----
    float* outp = out + (size_t)tok_base * EMBED + d0;
    const int tmax = n_tokens - tok_base;

    if (tmax >= TOK_TILE) {
        #pragma unroll 1
        for (int t = 0; t < TOK_TILE; ++t) {
            const ulonglong2* fp = reinterpret_cast<const ulonglong2*>(feats_s[t]);
            ulonglong2 qa = fp[0], qb = fp[1], qc = fp[2], qd = fp[3];
            unsigned long long f2[NFP] = {qa.x, qa.y, qb.x, qb.y, qc.x, qc.y, qd.x, qd.y};

            unsigned long long acc0 = 0ull, acc1 = 0ull;
            #pragma unroll
            for (int p = 0; p < NFP; ++p) {
                asm("fma.rn.f32x2 %0, %1, %2, %0;" : "+l"(acc0) : "l"(f2[p]), "l"(wreg[0][p]));
                asm("fma.rn.f32x2 %0, %1, %2, %0;" : "+l"(acc1) : "l"(f2[p]), "l"(wreg[1][p]));
            }
            float lo0, hi0, lo1, hi1;
            asm("mov.b64 {%0, %1}, %2;" : "=f"(lo0), "=f"(hi0) : "l"(acc0));
            asm("mov.b64 {%0, %1}, %2;" : "=f"(lo1), "=f"(hi1) : "l"(acc1));

            float2 o = make_float2(lo0 + hi0, lo1 + hi1);
            __stcs(reinterpret_cast<float2*>(outp), o);
            outp += EMBED;
        }
    } else {
        #pragma unroll 1
        for (int t = 0; t < tmax; ++t) {
            const ulonglong2* fp = reinterpret_cast<const ulonglong2*>(feats_s[t]);
            ulonglong2 qa = fp[0], qb = fp[1], qc = fp[2], qd = fp[3];
            unsigned long long f2[NFP] = {qa.x, qa.y, qb.x, qb.y, qc.x, qc.y, qd.x, qd.y};

            unsigned long long acc0 = 0ull, acc1 = 0ull;
            #pragma unroll
            for (int p = 0; p < NFP; ++p) {
                asm("fma.rn.f32x2 %0, %1, %2, %0;" : "+l"(acc0) : "l"(f2[p]), "l"(wreg[0][p]));
                asm("fma.rn.f32x2 %0, %1, %2, %0;" : "+l"(acc1) : "l"(f2[p]), "l"(wreg[1][p]));
            }
            float lo0, hi0, lo1, hi1;
            asm("mov.b64 {%0, %1}, %2;" : "=f"(lo0), "=f"(hi0) : "l"(acc0));
            asm("mov.b64 {%0, %1}, %2;" : "=f"(lo1), "=f"(hi1) : "l"(acc1));

            float2 o = make_float2(lo0 + hi0, lo1 + hi1);
            __stcs(reinterpret_cast<float2*>(outp), o);
            outp += EMBED;
        }
    }
}

extern "C" void kernel_launch(void* const* d_in, const int* in_sizes, int n_in,
                              void* d_out, int out_size)
{
    const int*   token_ids = (const int*)  d_in[0];
    const float* c_table   = (const float*)d_in[1];
    const float* W         = (const float*)d_in[2];
    const float* scale_p   = (const float*)d_in[3];
    float*       out       = (float*)d_out;

    const int n_tokens = in_sizes[0];
    const int blocks   = (n_tokens + TOK_TILE - 1) / TOK_TILE;
    fractal_embed_kernel<<<blocks, NTHREADS>>>(token_ids, c_table, W, scale_p, out, n_tokens);
}

// round 5
// speedup vs baseline: 1.2550x; 1.2550x over previous
#include <cuda_runtime.h>
#include <cstdint>

#define EMBED     1024
#define STEPS     8
#define NF        16     // 2*STEPS features
#define NFP       8      // f32x2 feature pairs
#define TOK_TILE  128    // tokens per CTA
#define NTHREADS  256    // 256 threads * 4 dims = 1024 embed dims
#define DPT       4      // embed dims per thread

__device__ __forceinline__ unsigned long long pack2(float a, float b) {
    unsigned long long r;
    asm("mov.b64 %0, {%1, %2};" : "=l"(r) : "f"(a), "f"(b));
    return r;
}

__device__ __forceinline__ void load_feats(const float* fs, unsigned long long* f2) {
    const ulonglong2* fp = reinterpret_cast<const ulonglong2*>(fs);
    ulonglong2 qa = fp[0], qb = fp[1], qc = fp[2], qd = fp[3];
    f2[0] = qa.x; f2[1] = qa.y; f2[2] = qb.x; f2[3] = qb.y;
    f2[4] = qc.x; f2[5] = qc.y; f2[6] = qd.x; f2[7] = qd.y;
}

__global__ void __launch_bounds__(NTHREADS, 2)
fractal_embed_kernel(const int*   __restrict__ token_ids,
                     const float* __restrict__ c_table,
                     const float* __restrict__ W,
                     const float* __restrict__ scale_p,
                     float*       __restrict__ out,
                     int n_tokens)
{
    __shared__ __align__(16) float feats_s[TOK_TILE][NF];

    const int tid      = threadIdx.x;
    const int tok_base = blockIdx.x * TOK_TILE;
    if (tok_base >= n_tokens) return;
    const float scale  = *scale_p;

    // ---- Phase A: Julia features (128 threads, one token each) ----
    if (tid < TOK_TILE && tok_base + tid < n_tokens) {
        const int   tok = token_ids[tok_base + tid];
        const float cr  = c_table[2 * tok];
        const float ci  = c_table[2 * tok + 1];
        float zr = 0.f, zi = 0.f;
        #pragma unroll
        for (int s = 0; s < STEPS; ++s) {
            const float nzr = zr * zr - zi * zi + cr;
            const float nzi = 2.f * zr * zi + ci;
            zr = nzr; zi = nzi;
            feats_s[tid][2 * s]     = zr;
            feats_s[tid][2 * s + 1] = zi;
        }
    }

    // ---- W slice: 4 rows x 16 feats, scale folded, f32x2-packed (32 u64) ----
    const int d0 = tid * DPT;
    unsigned long long wreg[DPT][NFP];
    {
        const float2* wp = reinterpret_cast<const float2*>(W + (size_t)d0 * NF);
        #pragma unroll
        for (int j = 0; j < DPT; ++j) {
            #pragma unroll
            for (int p = 0; p < NFP; ++p) {
                float2 w = wp[j * NFP + p];
                wreg[j][p] = pack2(w.x * scale, w.y * scale);
            }
        }
    }
    __syncthreads();

    // ---- Phase B: 2-token interleaved sweep (8 independent FMA chains) ----
    float* outp = out + (size_t)tok_base * EMBED + d0;
    const int tmax = n_tokens - tok_base;

    if (tmax >= TOK_TILE) {
        #pragma unroll 1
        for (int t = 0; t < TOK_TILE; t += 2) {
            unsigned long long fA[NFP], fB[NFP];
            load_feats(feats_s[t],     fA);
            load_feats(feats_s[t + 1], fB);

            unsigned long long aA0 = 0ull, aA1 = 0ull, aA2 = 0ull, aA3 = 0ull;
            unsigned long long aB0 = 0ull, aB1 = 0ull, aB2 = 0ull, aB3 = 0ull;
            #pragma unroll
            for (int p = 0; p < NFP; ++p) {
                asm("fma.rn.f32x2 %0, %1, %2, %0;" : "+l"(aA0) : "l"(fA[p]), "l"(wreg[0][p]));
                asm("fma.rn.f32x2 %0, %1, %2, %0;" : "+l"(aB0) : "l"(fB[p]), "l"(wreg[0][p]));
                asm("fma.rn.f32x2 %0, %1, %2, %0;" : "+l"(aA1) : "l"(fA[p]), "l"(wreg[1][p]));
                asm("fma.rn.f32x2 %0, %1, %2, %0;" : "+l"(aB1) : "l"(fB[p]), "l"(wreg[1][p]));
                asm("fma.rn.f32x2 %0, %1, %2, %0;" : "+l"(aA2) : "l"(fA[p]), "l"(wreg[2][p]));
                asm("fma.rn.f32x2 %0, %1, %2, %0;" : "+l"(aB2) : "l"(fB[p]), "l"(wreg[2][p]));
                asm("fma.rn.f32x2 %0, %1, %2, %0;" : "+l"(aA3) : "l"(fA[p]), "l"(wreg[3][p]));
                asm("fma.rn.f32x2 %0, %1, %2, %0;" : "+l"(aB3) : "l"(fB[p]), "l"(wreg[3][p]));
            }

            float l0, h0, l1, h1, l2, h2, l3, h3;
            asm("mov.b64 {%0, %1}, %2;" : "=f"(l0), "=f"(h0) : "l"(aA0));
            asm("mov.b64 {%0, %1}, %2;" : "=f"(l1), "=f"(h1) : "l"(aA1));
            asm("mov.b64 {%0, %1}, %2;" : "=f"(l2), "=f"(h2) : "l"(aA2));
            asm("mov.b64 {%0, %1}, %2;" : "=f"(l3), "=f"(h3) : "l"(aA3));
            float4 oA = make_float4(l0 + h0, l1 + h1, l2 + h2, l3 + h3);
            asm("mov.b64 {%0, %1}, %2;" : "=f"(l0), "=f"(h0) : "l"(aB0));
            asm("mov.b64 {%0, %1}, %2;" : "=f"(l1), "=f"(h1) : "l"(aB1));
            asm("mov.b64 {%0, %1}, %2;" : "=f"(l2), "=f"(h2) : "l"(aB2));
            asm("mov.b64 {%0, %1}, %2;" : "=f"(l3), "=f"(h3) : "l"(aB3));
            float4 oB = make_float4(l0 + h0, l1 + h1, l2 + h2, l3 + h3);

            __stcs(reinterpret_cast<float4*>(outp), oA);
            __stcs(reinterpret_cast<float4*>(outp + EMBED), oB);
            outp += 2 * EMBED;
        }
    } else {
        #pragma unroll 1
        for (int t = 0; t < tmax; ++t) {
            unsigned long long fA[NFP];
            load_feats(feats_s[t], fA);
            unsigned long long a0 = 0ull, a1 = 0ull, a2 = 0ull, a3 = 0ull;
            #pragma unroll
            for (int p = 0; p < NFP; ++p) {
                asm("fma.rn.f32x2 %0, %1, %2, %0;" : "+l"(a0) : "l"(fA[p]), "l"(wreg[0][p]));
                asm("fma.rn.f32x2 %0, %1, %2, %0;" : "+l"(a1) : "l"(fA[p]), "l"(wreg[1][p]));
                asm("fma.rn.f32x2 %0, %1, %2, %0;" : "+l"(a2) : "l"(fA[p]), "l"(wreg[2][p]));
                asm("fma.rn.f32x2 %0, %1, %2, %0;" : "+l"(a3) : "l"(fA[p]), "l"(wreg[3][p]));
            }
            float l0, h0, l1, h1, l2, h2, l3, h3;
            asm("mov.b64 {%0, %1}, %2;" : "=f"(l0), "=f"(h0) : "l"(a0));
            asm("mov.b64 {%0, %1}, %2;" : "=f"(l1), "=f"(h1) : "l"(a1));
            asm("mov.b64 {%0, %1}, %2;" : "=f"(l2), "=f"(h2) : "l"(a2));
            asm("mov.b64 {%0, %1}, %2;" : "=f"(l3), "=f"(h3) : "l"(a3));
            float4 o = make_float4(l0 + h0, l1 + h1, l2 + h2, l3 + h3);
            __stcs(reinterpret_cast<float4*>(outp), o);
            outp += EMBED;
        }
    }
}

extern "C" void kernel_launch(void* const* d_in, const int* in_sizes, int n_in,
                              void* d_out, int out_size)
{
    const int*   token_ids = (const int*)  d_in[0];
    const float* c_table   = (const float*)d_in[1];
    const float* W         = (const float*)d_in[2];
    const float* scale_p   = (const float*)d_in[3];
    float*       out       = (float*)d_out;

    const int n_tokens = in_sizes[0];
    const int blocks   = (n_tokens + TOK_TILE - 1) / TOK_TILE;
    fractal_embed_kernel<<<blocks, NTHREADS>>>(token_ids, c_table, W, scale_p, out, n_tokens);
}